// round 14
// baseline (speedup 1.0000x reference)
#include <cuda_runtime.h>
#include <cstddef>

#define BH 16
#define NSEQ 8192
#define DIM 64
#define MLAND 256
#define KW 33
#define PADW 16
#define NSPLIT 8
#define SPLEN (NSEQ/NSPLIT)   // 1024

typedef unsigned long long ull;

// ---------------- f32x2 packed-FMA helpers ----------------
#define FMA2(d,a,b,c) asm("fma.rn.f32x2 %0, %1, %2, %3;" : "=l"(d) : "l"(a), "l"(b), "l"(c))
#define MUL2(d,a,b)   asm("mul.rn.f32x2 %0, %1, %2;"     : "=l"(d) : "l"(a), "l"(b))
#define ADD2(d,a,b)   asm("add.rn.f32x2 %0, %1, %2;"     : "=l"(d) : "l"(a), "l"(b))
__device__ __forceinline__ ull dup2(float x){ ull r; asm("mov.b64 %0, {%1, %1};" : "=l"(r) : "f"(x)); return r; }
__device__ __forceinline__ ull pk2(float lo, float hi){ ull r; asm("mov.b64 %0, {%1, %2};" : "=l"(r) : "f"(lo), "f"(hi)); return r; }
__device__ __forceinline__ void unpk(ull p, float& lo, float& hi){ asm("mov.b64 {%0, %1}, %2;" : "=f"(lo), "=f"(hi) : "l"(p)); }
__device__ __forceinline__ ull ld64s(const float* p){ return *reinterpret_cast<const ull*>(p); }

// ---------------- scratch ----------------
static __device__ float g_QL[BH*MLAND*DIM];
static __device__ float g_KL[BH*MLAND*DIM];
static __device__ float g_A2[BH*MLAND*MLAND];
static __device__ float g_Z [BH*MLAND*MLAND];
static __device__ float g_Z2[BH*MLAND*MLAND];
static __device__ float g_XZ[BH*MLAND*MLAND];
static __device__ float g_U [BH*MLAND*MLAND];
static __device__ float g_Wm[BH*MLAND*MLAND];
static __device__ float g_T [BH*MLAND*DIM];
static __device__ float g_W2[BH*MLAND*DIM];
static __device__ float g_pacc[BH*4*NSPLIT*64*64];
static __device__ float g_pm [BH*4*NSPLIT*64];
static __device__ float g_pl [BH*4*NSPLIT*64];
static __device__ float g_cmax[BH];

// ---------------- landmarks ----------------
__global__ void landmark_kernel(const float* __restrict__ q, const float* __restrict__ k){
    int bh = blockIdx.y, mr = blockIdx.x, c = threadIdx.x;
    const float* qb = q + ((size_t)bh*NSEQ + (size_t)mr*32)*DIM + c;
    const float* kb = k + ((size_t)bh*NSEQ + (size_t)mr*32)*DIM + c;
    float sq = 0.f, sk = 0.f;
#pragma unroll
    for(int t=0;t<32;t++){ sq += qb[(size_t)t*DIM]; sk += kb[(size_t)t*DIM]; }
    g_QL[(bh*MLAND+mr)*DIM+c] = sq*(1.f/32.f);
    g_KL[(bh*MLAND+mr)*DIM+c] = sk*(1.f/32.f);
}

// ---------------- attn2: softmax(QL@KL^T) -> g_A2, register softmax ----------------
// grid (8, BH), 256 threads (ty=tid>>5 in 0..7 = warp, tx=tid&31). 32 rows/CTA.
__global__ void attn2_kernel(){
    __shared__ float As[64*34];      // [c][row]
    __shared__ ull  Bs2[64*65];      // [c][j] dup'd
    int bh = blockIdx.y; int r0 = blockIdx.x*32;
    int tid = threadIdx.x, tx = tid&31, ty = tid>>5;
#pragma unroll
    for(int rep=0; rep<8; rep++){
        int p = rep*256+tid; int r = p>>6, c = p&63;
        As[c*34 + r] = g_QL[((size_t)bh*MLAND + r0 + r)*DIM + c];
    }
    float s_all[4][8];
    for(int jt=0; jt<4; jt++){
#pragma unroll
        for(int rep=0; rep<16; rep++){
            int p = rep*256+tid; int j = p>>6, c = p&63;
            Bs2[c*65 + j] = dup2(g_KL[((size_t)bh*MLAND + jt*64 + j)*DIM + c]);
        }
        __syncthreads();
        ull acc[2][2] = {};
#pragma unroll 8
        for(int c=0;c<64;c++){
            ull a0 = ld64s(&As[c*34 + ty*4]);
            ull a1 = ld64s(&As[c*34 + ty*4+2]);
            ull b0 = Bs2[c*65 + tx];
            ull b1 = Bs2[c*65 + tx+32];
            FMA2(acc[0][0], a0,b0,acc[0][0]);
            FMA2(acc[0][1], a0,b1,acc[0][1]);
            FMA2(acc[1][0], a1,b0,acc[1][0]);
            FMA2(acc[1][1], a1,b1,acc[1][1]);
        }
#pragma unroll
        for(int p=0;p<2;p++)
#pragma unroll
            for(int s=0;s<2;s++){
                float lo,hi; unpk(acc[p][s],lo,hi);
                s_all[2*p][jt*2+s] = lo;
                s_all[2*p+1][jt*2+s] = hi;
            }
        __syncthreads();
    }
#pragma unroll
    for(int r=0;r<4;r++){
        float mx = -1e30f;
#pragma unroll
        for(int j=0;j<8;j++) mx = fmaxf(mx, s_all[r][j]);
#pragma unroll
        for(int o=16;o>0;o>>=1) mx = fmaxf(mx, __shfl_xor_sync(0xffffffffu, mx, o));
        float sm = 0.f;
#pragma unroll
        for(int j=0;j<8;j++){ float e = expf(s_all[r][j]-mx); s_all[r][j]=e; sm+=e; }
#pragma unroll
        for(int o=16;o>0;o>>=1) sm += __shfl_xor_sync(0xffffffffu, sm, o);
        float inv = 1.f/sm;
        int grow = (bh*MLAND + r0 + ty*4 + r);
#pragma unroll
        for(int j=0;j<8;j++)
            g_A2[(size_t)grow*MLAND + (j>>1)*64 + tx + 32*(j&1)] = s_all[r][j]*inv;
    }
}

// ---------------- cmax = max column sum (rowsums == 1 for softmax) ----------------
__global__ void colrow_kernel(){
    __shared__ float red[256];
    int bh = blockIdx.x, tid = threadIdx.x;
    const float* A = g_A2 + (size_t)bh*MLAND*MLAND;
    float cs=0.f;
    for(int i=0;i<MLAND;i++) cs += A[(size_t)i*MLAND+tid];
    red[tid]=cs; __syncthreads();
    for(int s=128;s>0;s>>=1){ if(tid<s) red[tid]=fmaxf(red[tid],red[tid+s]); __syncthreads(); }
    if(tid==0) g_cmax[bh]=red[0];
}

// ---------------- z0 = x^T / (global max colsum) ----------------
__global__ void zinit_kernel(){
    __shared__ float tile[64*65];
    int bh = blockIdx.z;
    int i0 = blockIdx.x*64, j0 = blockIdx.y*64;
    int tid = threadIdx.x;
#pragma unroll
    for(int rep=0; rep<16; rep++){
        int p = rep*256+tid; int r = p>>6, c = p&63;
        tile[r*65+c] = g_A2[((size_t)bh*MLAND + i0+r)*MLAND + j0+c];
    }
    __syncthreads();
    float mc=0.f;
#pragma unroll
    for(int t=0;t<BH;t++) mc=fmaxf(mc,g_cmax[t]);
    float inv = 1.f/mc;
#pragma unroll
    for(int rep=0; rep<16; rep++){
        int p = rep*256+tid; int r = p>>6, c = p&63;
        g_Z[((size_t)bh*MLAND + j0+r)*MLAND + i0+c] = tile[c*65+r]*inv;
    }
}

// ---------------- batched 256^3 GEMM (pre-dup'd A, paired B) ----------------
#define KKM 32
__global__ void mmex_kernel(const float* __restrict__ A, const float* __restrict__ B,
                            float* __restrict__ C, float s, float dg, float tt){
    __shared__ ull  As2[KKM*65];     // [kq][i] dup'd
    __shared__ float Bs[KKM*68];     // [kq][j]
    int bh = blockIdx.z;
    A += (size_t)bh*MLAND*MLAND; B += (size_t)bh*MLAND*MLAND; C += (size_t)bh*MLAND*MLAND;
    int i0 = blockIdx.x*64, j0 = blockIdx.y*64;
    int tid = threadIdx.x, tx = tid&15, ty = tid>>4;
    ull acc[4][2] = {};              // [row s (ty+16s)][colpair]
    for(int kk=0; kk<MLAND; kk+=KKM){
#pragma unroll
        for(int rep=0; rep<8; rep++){
            int p = rep*256+tid;
            int kq = p&31, i = p>>5;
            As2[kq*65+i] = dup2(A[(size_t)(i0+i)*MLAND + kk + kq]);
            int j = p&63, kb = p>>6;
            Bs[kb*68+j] = B[(size_t)(kk+kb)*MLAND + j0 + j];
        }
        __syncthreads();
#pragma unroll 8
        for(int kq=0; kq<KKM; kq++){
            ull a0 = As2[kq*65+ty];
            ull a1 = As2[kq*65+ty+16];
            ull a2 = As2[kq*65+ty+32];
            ull a3 = As2[kq*65+ty+48];
            ull b0 = ld64s(&Bs[kq*68+tx*4]);
            ull b1 = ld64s(&Bs[kq*68+tx*4+2]);
            FMA2(acc[0][0], a0,b0,acc[0][0]); FMA2(acc[0][1], a0,b1,acc[0][1]);
            FMA2(acc[1][0], a1,b0,acc[1][0]); FMA2(acc[1][1], a1,b1,acc[1][1]);
            FMA2(acc[2][0], a2,b0,acc[2][0]); FMA2(acc[2][1], a2,b1,acc[2][1]);
            FMA2(acc[3][0], a3,b0,acc[3][0]); FMA2(acc[3][1], a3,b1,acc[3][1]);
        }
        __syncthreads();
    }
#pragma unroll
    for(int ss=0;ss<4;ss++){
        int gi = i0 + ty + 16*ss;
        float c0,c1,c2,c3;
        unpk(acc[ss][0],c0,c1); unpk(acc[ss][1],c2,c3);
        float o[4] = {s*c0, s*c1, s*c2, s*c3};
#pragma unroll
        for(int c=0;c<4;c++) if(gi == j0+tx*4+c) o[c] += dg;
        if(tt != 0.f){
            float4 a4 = *reinterpret_cast<const float4*>(&A[(size_t)gi*MLAND + j0 + tx*4]);
            o[0] += tt*a4.x; o[1] += tt*a4.y; o[2] += tt*a4.z; o[3] += tt*a4.w;
        }
        *reinterpret_cast<float4*>(&C[(size_t)gi*MLAND + j0 + tx*4]) = make_float4(o[0],o[1],o[2],o[3]);
    }
}

// ---------------- sim3 flash (ty8 x tx32, dup'd K/V) ----------------
// grid (4 qblk, NSPLIT, BH), 256 threads, dyn smem 100352 B
__global__ void flash3_kernel(const float* __restrict__ k, const float* __restrict__ v){
    extern __shared__ float sm_[];
    float* qs = sm_;                         // [c][row] 64x66
    float* Ps = qs + 64*66;                  // [j][row] 64x66
    ull*  kt = (ull*)(Ps + 64*66);           // [c][j] dup 64x65
    ull*  vs = kt + 64*65;                   // [j][d] dup 64x65
    int qb = blockIdx.x, sp = blockIdx.y, bh = blockIdx.z;
    int tid = threadIdx.x, tx = tid&31, ty = tid>>5;
#pragma unroll
    for(int rep=0; rep<16; rep++){
        int p = rep*256+tid; int r = p>>6, c = p&63;
        qs[c*66+r] = g_QL[((size_t)bh*MLAND + qb*64 + r)*DIM + c];
    }
    float m[8], l[8];
    ull acc[4][2] = {};                      // [rowpair p (8ty+2p)][col s]
#pragma unroll
    for(int r=0;r<8;r++){ m[r]=-1e30f; l[r]=0.f; }
    for(int t=0; t<SPLEN/64; t++){
        int j0 = sp*SPLEN + t*64;
#pragma unroll
        for(int rep=0; rep<16; rep++){
            int p = rep*256+tid; int j = p>>6, c = p&63;
            kt[c*65 + j] = dup2(k[((size_t)bh*NSEQ + j0+j)*DIM + c]);
            vs[j*65 + c] = dup2(v[((size_t)bh*NSEQ + j0+j)*DIM + c]);
        }
        __syncthreads();
        ull s2[4][2] = {};
#pragma unroll 8
        for(int c=0;c<64;c++){
            ull b0 = kt[c*65 + tx];
            ull b1 = kt[c*65 + tx+32];
#pragma unroll
            for(int p=0;p<4;p++){
                ull ap = ld64s(&qs[c*66 + ty*8 + 2*p]);
                FMA2(s2[p][0], ap, b0, s2[p][0]);
                FMA2(s2[p][1], ap, b1, s2[p][1]);
            }
        }
        float s[8][2];
#pragma unroll
        for(int p=0;p<4;p++)
#pragma unroll
            for(int cc=0;cc<2;cc++) unpk(s2[p][cc], s[2*p][cc], s[2*p+1][cc]);
        float scale[8];
#pragma unroll
        for(int r=0;r<8;r++){
            float tmax = fmaxf(s[r][0], s[r][1]);
#pragma unroll
            for(int o=16;o>0;o>>=1) tmax = fmaxf(tmax, __shfl_xor_sync(0xffffffffu, tmax, o));
            float mn = fmaxf(m[r], tmax);
            scale[r] = expf(m[r]-mn);
            float p0 = expf(s[r][0]-mn), p1 = expf(s[r][1]-mn);
            float rs = p0 + p1;
#pragma unroll
            for(int o=16;o>0;o>>=1) rs += __shfl_xor_sync(0xffffffffu, rs, o);
            l[r] = l[r]*scale[r] + rs;
            m[r] = mn;
            s[r][0]=p0; s[r][1]=p1;
        }
        // store P^T: Ps[j][row]
#pragma unroll
        for(int p=0;p<4;p++){
#pragma unroll
            for(int cc=0;cc<2;cc++){
                ull pv = pk2(s[2*p][cc], s[2*p+1][cc]);
                *reinterpret_cast<ull*>(&Ps[(tx+32*cc)*66 + ty*8 + 2*p]) = pv;
            }
            ull sc = pk2(scale[2*p], scale[2*p+1]);
            MUL2(acc[p][0], acc[p][0], sc);
            MUL2(acc[p][1], acc[p][1], sc);
        }
        __syncthreads();
#pragma unroll 8
        for(int j=0;j<64;j++){
            ull b0 = vs[j*65 + tx];
            ull b1 = vs[j*65 + tx+32];
#pragma unroll
            for(int p=0;p<4;p++){
                ull ap = ld64s(&Ps[j*66 + ty*8 + 2*p]);
                FMA2(acc[p][0], ap, b0, acc[p][0]);
                FMA2(acc[p][1], ap, b1, acc[p][1]);
            }
        }
        __syncthreads();
    }
    int base = ((bh*4+qb)*NSPLIT + sp);
#pragma unroll
    for(int p=0;p<4;p++){
        float o0lo,o0hi,o1lo,o1hi;
        unpk(acc[p][0],o0lo,o0hi); unpk(acc[p][1],o1lo,o1hi);
        int i_lo = ty*8 + 2*p, i_hi = i_lo+1;
        g_pacc[((size_t)base*64 + i_lo)*64 + tx]    = o0lo;
        g_pacc[((size_t)base*64 + i_hi)*64 + tx]    = o0hi;
        g_pacc[((size_t)base*64 + i_lo)*64 + tx+32] = o1lo;
        g_pacc[((size_t)base*64 + i_hi)*64 + tx+32] = o1hi;
    }
    if(tx==0){
#pragma unroll
        for(int r=0;r<8;r++){
            g_pm[base*64 + ty*8+r] = m[r];
            g_pl[base*64 + ty*8+r] = l[r];
        }
    }
}

// ---------------- merge flash partials -> g_T ----------------
__global__ void merge3_kernel(){
    int bq = blockIdx.x;
    int tid = threadIdx.x;
    int i = tid>>2, g = tid&3;
    float M = -1e30f;
#pragma unroll
    for(int s=0;s<NSPLIT;s++) M = fmaxf(M, g_pm[(bq*NSPLIT+s)*64 + i]);
    float L = 0.f;
#pragma unroll
    for(int s=0;s<NSPLIT;s++) L += g_pl[(bq*NSPLIT+s)*64 + i]*expf(g_pm[(bq*NSPLIT+s)*64+i]-M);
    float invL = 1.f/L;
    float o[16];
#pragma unroll
    for(int d=0;d<16;d++) o[d]=0.f;
#pragma unroll
    for(int s=0;s<NSPLIT;s++){
        float w = expf(g_pm[(bq*NSPLIT+s)*64+i]-M);
        const float* pa = &g_pacc[((size_t)(bq*NSPLIT+s)*64 + i)*64 + g*16];
#pragma unroll
        for(int d=0;d<16;d++) o[d] += w*pa[d];
    }
    int bh = bq>>2, qb = bq&3;
    float* To = &g_T[((size_t)bh*MLAND + qb*64 + i)*DIM + g*16];
#pragma unroll
    for(int d=0;d<16;d++) To[d] = o[d]*invL;
}

// ---------------- W2 = Z @ T ----------------
__global__ void ab_kernel(const float* __restrict__ A, const float* __restrict__ B,
                          float* __restrict__ C, int rows, int K){
    __shared__ float Vs[64][64];
    __shared__ float Ss[32][64];
    int bh = blockIdx.y;
    const float* Ab = A + (size_t)bh*rows*K;
    const float* Bb = B + (size_t)bh*K*DIM;
    float*       Cb = C + (size_t)bh*rows*DIM;
    int r0 = blockIdx.x*32;
    int tid = threadIdx.x;
    int d = tid&31, ig = tid>>5;
    float acc[4][2] = {};
    for(int kt=0; kt<K; kt+=64){
#pragma unroll
        for(int rep=0; rep<16; rep++){
            int p = rep*256+tid; int j = p>>6, c = p&63;
            Vs[j][c] = Bb[(size_t)(kt+j)*DIM + c];
        }
#pragma unroll
        for(int rep=0; rep<8; rep++){
            int p = rep*256+tid; int rr = p>>6, jj = p&63;
            Ss[rr][jj] = Ab[(size_t)(r0+rr)*K + kt + jj];
        }
        __syncthreads();
#pragma unroll 4
        for(int j=0;j<64;j++){
            float v0 = Vs[j][d], v1 = Vs[j][d+32];
#pragma unroll
            for(int r=0;r<4;r++){
                float sv = Ss[ig+8*r][j];
                acc[r][0] += sv*v0;
                acc[r][1] += sv*v1;
            }
        }
        __syncthreads();
    }
#pragma unroll
    for(int r=0;r<4;r++){
        Cb[(size_t)(r0+ig+8*r)*DIM + d]      = acc[r][0];
        Cb[(size_t)(r0+ig+8*r)*DIM + d + 32] = acc[r][1];
    }
}

// ---------------- sim1 fused (register softmax + dup'd operands) ----------------
// grid (256, BH), 256 threads (ty8 x tx32), dyn smem 76800 B
__global__ void fused1_kernel(const float* __restrict__ q, const float* __restrict__ v,
                              const float* __restrict__ cw, float* __restrict__ out){
    extern __shared__ float sm_[];
    float* Ss = sm_;                         // P^T [col][row] 256x34; later Vv/outT overlay
    float* As = Ss + 256*34;                 // [c][row] 64x34
    ull*  Bs2 = (ull*)(As + 64*34);          // [c or jj][x] dup 64x65
    float* Vv  = Ss;                         // [row 96][66]
    float* outT = Ss + 96*66;                // [row 32][68]
    __shared__ ull ws2[KW];
    int bh = blockIdx.y;
    int r0 = blockIdx.x*32;
    int tid = threadIdx.x, tx = tid&31, ty = tid>>5;
    if(tid<KW) ws2[tid] = dup2(cw[(bh&7)*KW + tid]);
#pragma unroll
    for(int rep=0; rep<8; rep++){
        int p = rep*256+tid; int r = p>>6, c = p&63;
        As[c*34 + r] = q[((size_t)bh*NSEQ + r0+r)*DIM + c];
    }
    // phase 1: S = q @ KL^T, scores in registers
    float s_all[4][8];
    for(int jt=0; jt<4; jt++){
#pragma unroll
        for(int rep=0; rep<16; rep++){
            int p = rep*256+tid; int j = p>>6, c = p&63;
            Bs2[c*65 + j] = dup2(g_KL[((size_t)bh*MLAND + jt*64 + j)*DIM + c]);
        }
        __syncthreads();
        ull acc[2][2] = {};
#pragma unroll 8
        for(int c=0;c<64;c++){
            ull a0 = ld64s(&As[c*34 + ty*4]);
            ull a1 = ld64s(&As[c*34 + ty*4+2]);
            ull b0 = Bs2[c*65 + tx];
            ull b1 = Bs2[c*65 + tx+32];
            FMA2(acc[0][0], a0,b0,acc[0][0]);
            FMA2(acc[0][1], a0,b1,acc[0][1]);
            FMA2(acc[1][0], a1,b0,acc[1][0]);
            FMA2(acc[1][1], a1,b1,acc[1][1]);
        }
#pragma unroll
        for(int p=0;p<2;p++)
#pragma unroll
            for(int s=0;s<2;s++){
                float lo,hi; unpk(acc[p][s],lo,hi);
                s_all[2*p][jt*2+s] = lo;
                s_all[2*p+1][jt*2+s] = hi;
            }
        __syncthreads();
    }
    // phase 2: register softmax + store P^T (row pairs adjacent)
#pragma unroll
    for(int r=0;r<4;r++){
        float mx = -1e30f;
#pragma unroll
        for(int j=0;j<8;j++) mx = fmaxf(mx, s_all[r][j]);
#pragma unroll
        for(int o=16;o>0;o>>=1) mx = fmaxf(mx, __shfl_xor_sync(0xffffffffu, mx, o));
        float sm = 0.f;
#pragma unroll
        for(int j=0;j<8;j++){ float e = expf(s_all[r][j]-mx); s_all[r][j]=e; sm+=e; }
#pragma unroll
        for(int o=16;o>0;o>>=1) sm += __shfl_xor_sync(0xffffffffu, sm, o);
        float inv = 1.f/sm;
#pragma unroll
        for(int j=0;j<8;j++) s_all[r][j] *= inv;
    }
#pragma unroll
    for(int j=0;j<8;j++){
        int col = (j>>1)*64 + tx + 32*(j&1);
        *reinterpret_cast<ull*>(&Ss[col*34 + ty*4])   = pk2(s_all[0][j], s_all[1][j]);
        *reinterpret_cast<ull*>(&Ss[col*34 + ty*4+2]) = pk2(s_all[2][j], s_all[3][j]);
    }
    __syncthreads();
    // phase 3: out = P @ W2
    ull oacc[2][2] = {};
    for(int jt2=0; jt2<4; jt2++){
#pragma unroll
        for(int rep=0; rep<16; rep++){
            int p = rep*256+tid; int jj = p>>6, d = p&63;
            Bs2[jj*65 + d] = dup2(g_W2[((size_t)bh*MLAND + jt2*64 + jj)*DIM + d]);
        }
        __syncthreads();
#pragma unroll 8
        for(int jj=0;jj<64;jj++){
            ull a0 = ld64s(&Ss[(jt2*64+jj)*34 + ty*4]);
            ull a1 = ld64s(&Ss[(jt2*64+jj)*34 + ty*4+2]);
            ull b0 = Bs2[jj*65 + tx];
            ull b1 = Bs2[jj*65 + tx+32];
            FMA2(oacc[0][0], a0,b0,oacc[0][0]);
            FMA2(oacc[0][1], a0,b1,oacc[0][1]);
            FMA2(oacc[1][0], a1,b0,oacc[1][0]);
            FMA2(oacc[1][1], a1,b1,oacc[1][1]);
        }
        __syncthreads();
    }
    // stage GEMM result to outT (overlays Ss tail; P no longer needed)
#pragma unroll
    for(int p=0;p<2;p++)
#pragma unroll
        for(int s=0;s<2;s++){
            float lo,hi; unpk(oacc[p][s],lo,hi);
            outT[(ty*4+2*p  )*68 + tx + 32*s] = lo;
            outT[(ty*4+2*p+1)*68 + tx + 32*s] = hi;
        }
    // load conv halo (overlays Ss head)
#pragma unroll
    for(int rep=0; rep<24; rep++){
        int p = rep*256+tid; int rr = p>>6, c = p&63;
        int gr = r0 - PADW + rr;
        Vv[rr*66+c] = (gr>=0 && gr<NSEQ) ? v[((size_t)bh*NSEQ+gr)*DIM + c] : 0.f;
    }
    __syncthreads();
    // phase 4: conv with d-contiguous remap, add, store
    {
        int tx16 = tid&15, ty16 = tid>>4;   // rows ty16*2+{0,1}, d = tx16*4..+3
        ull cacc[2][2] = {};
#pragma unroll
        for(int kk=0; kk<KW; kk++){
            ull wd = ws2[kk];
#pragma unroll
            for(int rr=0;rr<2;rr++){
                int vr = ty16*2+rr+kk;
                ull v0 = ld64s(&Vv[vr*66 + tx16*4]);
                ull v1 = ld64s(&Vv[vr*66 + tx16*4+2]);
                FMA2(cacc[rr][0], wd, v0, cacc[rr][0]);
                FMA2(cacc[rr][1], wd, v1, cacc[rr][1]);
            }
        }
#pragma unroll
        for(int rr=0;rr<2;rr++){
            int lr = ty16*2+rr;
            float4 gacc = *reinterpret_cast<float4*>(&outT[lr*68 + tx16*4]);
            float c0,c1,c2,c3;
            unpk(cacc[rr][0],c0,c1); unpk(cacc[rr][1],c2,c3);
            *reinterpret_cast<float4*>(&out[((size_t)bh*NSEQ + r0 + lr)*DIM + tx16*4]) =
                make_float4(gacc.x+c0, gacc.y+c1, gacc.z+c2, gacc.w+c3);
        }
    }
}

// ---------------- launch (fork/join overlap) ----------------
static cudaStream_t g_s1 = nullptr;
static cudaEvent_t  g_ev0 = nullptr, g_ev1 = nullptr;

extern "C" void kernel_launch(void* const* d_in, const int* in_sizes, int n_in,
                              void* d_out, int out_size){
    const float* q  = (const float*)d_in[0];
    const float* k  = (const float*)d_in[1];
    const float* v  = (const float*)d_in[2];
    const float* cw = (const float*)d_in[3];
    float* out = (float*)d_out;

    if(!g_s1){
        cudaStreamCreateWithFlags(&g_s1, cudaStreamNonBlocking);
        cudaEventCreateWithFlags(&g_ev0, cudaEventDisableTiming);
        cudaEventCreateWithFlags(&g_ev1, cudaEventDisableTiming);
    }

    float *pA2,*pZ,*pZ2,*pXZ,*pU,*pWm,*pT,*pW2;
    cudaGetSymbolAddress((void**)&pA2, g_A2);
    cudaGetSymbolAddress((void**)&pZ,  g_Z);
    cudaGetSymbolAddress((void**)&pZ2, g_Z2);
    cudaGetSymbolAddress((void**)&pXZ, g_XZ);
    cudaGetSymbolAddress((void**)&pU,  g_U);
    cudaGetSymbolAddress((void**)&pWm, g_Wm);
    cudaGetSymbolAddress((void**)&pT,  g_T);
    cudaGetSymbolAddress((void**)&pW2, g_W2);

    const int FL3_SMEM = 2*64*66*4 + 2*64*65*8;       // 100352
    const int FU1_SMEM = 256*34*4 + 64*34*4 + 64*65*8; // 76800
    cudaFuncSetAttribute(flash3_kernel, cudaFuncAttributeMaxDynamicSharedMemorySize, FL3_SMEM);
    cudaFuncSetAttribute(fused1_kernel, cudaFuncAttributeMaxDynamicSharedMemorySize, FU1_SMEM);

    // landmarks (both branches need QL/KL)
    landmark_kernel<<<dim3(MLAND,BH), DIM>>>(q, k);

    // fork: sim3 branch
    cudaEventRecord(g_ev0, 0);
    cudaStreamWaitEvent(g_s1, g_ev0, 0);
    flash3_kernel<<<dim3(4,NSPLIT,BH), 256, FL3_SMEM, g_s1>>>(k, v);
    merge3_kernel<<<BH*4, 256, 0, g_s1>>>();
    cudaEventRecord(g_ev1, g_s1);

    // pinv branch
    attn2_kernel<<<dim3(8,BH), 256>>>();
    colrow_kernel<<<BH, 256>>>();
    zinit_kernel<<<dim3(4,4,BH), 256>>>();
    float* zc = pZ; float* zn = pZ2;
    for(int it=0; it<6; it++){
        mmex_kernel<<<dim3(4,4,BH), 256>>>(pA2, zc, pXZ, 1.f,  0.f,  0.f);
        mmex_kernel<<<dim3(4,4,BH), 256>>>(pXZ, pXZ, pU, 1.f, 15.f, -7.f);
        mmex_kernel<<<dim3(4,4,BH), 256>>>(pXZ, pU, pWm, -1.f, 13.f, 0.f);
        mmex_kernel<<<dim3(4,4,BH), 256>>>(zc,  pWm, zn, 0.25f, 0.f, 0.f);
        float* tsw = zc; zc = zn; zn = tsw;
    }

    // join
    cudaStreamWaitEvent(0, g_ev1, 0);
    ab_kernel<<<dim3(MLAND/32, BH), 256>>>(zc, pT, pW2, MLAND, MLAND);

    // sim1 fused
    fused1_kernel<<<dim3(NSEQ/32, BH), 256, FU1_SMEM>>>(q, v, cw, out);
}